// round 5
// baseline (speedup 1.0000x reference)
#include <cuda_runtime.h>

#define BB    2
#define SS    2048
#define TT    4096
#define HH    1024
#define GG    1024
#define G3    3072
#define FF    2048
#define EE    8
#define GRU_BLOCKS 128

__device__ float g_xw[(size_t)TT * G3];
__device__ float g_hs[(size_t)TT * GG];
__device__ float g_expr[(size_t)TT * GG];
__device__ float g_act[(size_t)(EE + 1) * TT * FF];   /* slot EE = shared expert */
__device__ float g_mean[BB * HH];
__device__ float g_h[2][BB * GG];
__device__ int   g_cnt[EE];
__device__ int   g_list[EE * TT];
__device__ float g_wt[EE * TT];
__device__ unsigned int g_bar;

__device__ __forceinline__ unsigned int ld_vol(const unsigned int* p) {
    unsigned int v;
    asm volatile("ld.volatile.global.u32 %0, [%1];" : "=r"(v) : "l"(p) : "memory");
    return v;
}
__device__ __forceinline__ float sigf(float x) { return 1.0f / (1.0f + expf(-x)); }

__global__ void init_kernel() {
    int i = threadIdx.x;
    if (i < EE) g_cnt[i] = 0;
    if (i == 0) g_bar = 0u;
}

__global__ void mean_kernel(const float* __restrict__ hid) {
    int idx = blockIdx.x * blockDim.x + threadIdx.x;
    if (idx >= BB * HH) return;
    int b = idx / HH, h = idx % HH;
    const float* p = hid + (size_t)b * SS * HH + h;
    float s0 = 0.f, s1 = 0.f, s2 = 0.f, s3 = 0.f;
    for (int s = 0; s < SS; s += 4) {
        s0 += p[(size_t)(s + 0) * HH];
        s1 += p[(size_t)(s + 1) * HH];
        s2 += p[(size_t)(s + 2) * HH];
        s3 += p[(size_t)(s + 3) * HH];
    }
    g_mean[idx] = (s0 + s1 + s2 + s3) * (1.0f / (float)SS);
}

__global__ void h0_kernel(const float* __restrict__ ctxw, const float* __restrict__ ctxb) {
    int wid  = (blockIdx.x * blockDim.x + threadIdx.x) >> 5;
    int lane = threadIdx.x & 31;
    if (wid >= BB * GG) return;
    int b = wid >> 10, g = wid & 1023;
    const float4* wv = (const float4*)(ctxw + (size_t)g * HH);
    const float4* mv = (const float4*)(g_mean + b * HH);
    float acc = 0.f;
#pragma unroll
    for (int i = 0; i < 8; i++) {
        float4 a = wv[lane + 32 * i];
        float4 m = mv[lane + 32 * i];
        acc += a.x * m.x + a.y * m.y + a.z * m.z + a.w * m.w;
    }
#pragma unroll
    for (int o = 16; o > 0; o >>= 1) acc += __shfl_xor_sync(0xffffffffu, acc, o);
    if (lane == 0) g_h[0][b * GG + g] = acc + ctxb[g];
}

/* C[M,N] = A[M,K] @ B[N,K]^T ; M,N mult of 64, K mult of 16 */
__global__ __launch_bounds__(256) void sgemm_nt(
    const float* __restrict__ A, const float* __restrict__ B, float* __restrict__ C,
    int M, int N, int K)
{
    __shared__ float As[16][68];
    __shared__ float Bs[16][68];
    int tid  = threadIdx.x;
    int row0 = blockIdx.y * 64, col0 = blockIdx.x * 64;
    int lm = tid >> 2, lk = (tid & 3) << 2;
    const float* Ap = A + (size_t)(row0 + lm) * K + lk;
    const float* Bp = B + (size_t)(col0 + lm) * K + lk;
    int ty = tid >> 4, tx = tid & 15;
    float acc[4][4] = {};
    for (int k0 = 0; k0 < K; k0 += 16) {
        float4 av = *(const float4*)(Ap + k0);
        float4 bv = *(const float4*)(Bp + k0);
        As[lk + 0][lm] = av.x; As[lk + 1][lm] = av.y; As[lk + 2][lm] = av.z; As[lk + 3][lm] = av.w;
        Bs[lk + 0][lm] = bv.x; Bs[lk + 1][lm] = bv.y; Bs[lk + 2][lm] = bv.z; Bs[lk + 3][lm] = bv.w;
        __syncthreads();
#pragma unroll
        for (int kk = 0; kk < 16; kk++) {
            float4 a = *(const float4*)(&As[kk][ty << 2]);
            float4 b = *(const float4*)(&Bs[kk][tx << 2]);
            float aa[4] = {a.x, a.y, a.z, a.w};
            float bb[4] = {b.x, b.y, b.z, b.w};
#pragma unroll
            for (int i = 0; i < 4; i++)
#pragma unroll
                for (int j = 0; j < 4; j++)
                    acc[i][j] = fmaf(aa[i], bb[j], acc[i][j]);
        }
        __syncthreads();
    }
#pragma unroll
    for (int i = 0; i < 4; i++)
        *(float4*)(C + (size_t)(row0 + (ty << 2) + i) * N + col0 + (tx << 2)) =
            make_float4(acc[i][0], acc[i][1], acc[i][2], acc[i][3]);
}

/* act = silu(X Gw^T) * (X Uw^T). gather=0 -> dense M=T, slot EE. */
__global__ __launch_bounds__(256) void gateup_kernel(
    const float* __restrict__ X,
    const float* __restrict__ gw_base, const float* __restrict__ uw_base, int gather)
{
    int e = blockIdx.z;
    int M = gather ? g_cnt[e] : TT;
    int row0 = blockIdx.y * 64;
    if (row0 >= M) return;
    int col0 = blockIdx.x * 64;
    const float* gw = gw_base + (size_t)e * FF * HH;
    const float* uw = uw_base + (size_t)e * FF * HH;
    float* actout   = g_act + (size_t)(gather ? e : EE) * TT * FF;

    __shared__ float As[16][68];
    __shared__ float Gs[16][68];
    __shared__ float Us[16][68];
    int tid = threadIdx.x;
    int lm = tid >> 2, lk = (tid & 3) << 2;
    int i = row0 + lm;
    int srow = gather ? g_list[e * TT + min(i, M - 1)] : i;
    const float* Ap = X  + (size_t)srow * HH + lk;
    const float* Gp = gw + (size_t)(col0 + lm) * HH + lk;
    const float* Up = uw + (size_t)(col0 + lm) * HH + lk;
    int ty = tid >> 4, tx = tid & 15;
    float accg[4][4] = {};
    float accu[4][4] = {};
    for (int k0 = 0; k0 < HH; k0 += 16) {
        float4 av = *(const float4*)(Ap + k0);
        float4 gv = *(const float4*)(Gp + k0);
        float4 uv = *(const float4*)(Up + k0);
        As[lk + 0][lm] = av.x; As[lk + 1][lm] = av.y; As[lk + 2][lm] = av.z; As[lk + 3][lm] = av.w;
        Gs[lk + 0][lm] = gv.x; Gs[lk + 1][lm] = gv.y; Gs[lk + 2][lm] = gv.z; Gs[lk + 3][lm] = gv.w;
        Us[lk + 0][lm] = uv.x; Us[lk + 1][lm] = uv.y; Us[lk + 2][lm] = uv.z; Us[lk + 3][lm] = uv.w;
        __syncthreads();
#pragma unroll
        for (int kk = 0; kk < 16; kk++) {
            float4 a = *(const float4*)(&As[kk][ty << 2]);
            float4 g = *(const float4*)(&Gs[kk][tx << 2]);
            float4 u = *(const float4*)(&Us[kk][tx << 2]);
            float aa[4] = {a.x, a.y, a.z, a.w};
            float gg[4] = {g.x, g.y, g.z, g.w};
            float uu[4] = {u.x, u.y, u.z, u.w};
#pragma unroll
            for (int r = 0; r < 4; r++)
#pragma unroll
                for (int c = 0; c < 4; c++) {
                    accg[r][c] = fmaf(aa[r], gg[c], accg[r][c]);
                    accu[r][c] = fmaf(aa[r], uu[c], accu[r][c]);
                }
        }
        __syncthreads();
    }
#pragma unroll
    for (int r = 0; r < 4; r++) {
        int rr = row0 + (ty << 2) + r;
        if (rr < M) {
            float g0 = accg[r][0], g1 = accg[r][1], g2 = accg[r][2], g3 = accg[r][3];
            float4 o;
            o.x = (g0 / (1.0f + expf(-g0))) * accu[r][0];
            o.y = (g1 / (1.0f + expf(-g1))) * accu[r][1];
            o.z = (g2 / (1.0f + expf(-g2))) * accu[r][2];
            o.w = (g3 / (1.0f + expf(-g3))) * accu[r][3];
            *(float4*)(actout + (size_t)rr * FF + col0 + (tx << 2)) = o;
        }
    }
}

/* Y = act @ Dw^T. gather=0: plain store (shared, slot EE). gather=1: atomicAdd*wt */
__global__ __launch_bounds__(256) void down_kernel(
    const float* __restrict__ dw_base, float* __restrict__ out, int gather)
{
    int e = blockIdx.z;
    int M = gather ? g_cnt[e] : TT;
    int row0 = blockIdx.y * 64;
    if (row0 >= M) return;
    int col0 = blockIdx.x * 64;
    const float* Aact = g_act + (size_t)(gather ? e : EE) * TT * FF;
    const float* dw   = dw_base + (size_t)e * HH * FF;

    __shared__ float As[16][68];
    __shared__ float Bs[16][68];
    int tid = threadIdx.x;
    int lm = tid >> 2, lk = (tid & 3) << 2;
    int i  = min(row0 + lm, M - 1);
    const float* Ap = Aact + (size_t)i * FF + lk;
    const float* Bp = dw + (size_t)(col0 + lm) * FF + lk;
    int ty = tid >> 4, tx = tid & 15;
    float acc[4][4] = {};
    for (int k0 = 0; k0 < FF; k0 += 16) {
        float4 av = *(const float4*)(Ap + k0);
        float4 bv = *(const float4*)(Bp + k0);
        As[lk + 0][lm] = av.x; As[lk + 1][lm] = av.y; As[lk + 2][lm] = av.z; As[lk + 3][lm] = av.w;
        Bs[lk + 0][lm] = bv.x; Bs[lk + 1][lm] = bv.y; Bs[lk + 2][lm] = bv.z; Bs[lk + 3][lm] = bv.w;
        __syncthreads();
#pragma unroll
        for (int kk = 0; kk < 16; kk++) {
            float4 a = *(const float4*)(&As[kk][ty << 2]);
            float4 b = *(const float4*)(&Bs[kk][tx << 2]);
            float aa[4] = {a.x, a.y, a.z, a.w};
            float bb[4] = {b.x, b.y, b.z, b.w};
#pragma unroll
            for (int r = 0; r < 4; r++)
#pragma unroll
                for (int c = 0; c < 4; c++)
                    acc[r][c] = fmaf(aa[r], bb[c], acc[r][c]);
        }
        __syncthreads();
    }
    if (!gather) {
#pragma unroll
        for (int r = 0; r < 4; r++) {
            int rr = row0 + (ty << 2) + r;
            *(float4*)(out + (size_t)rr * HH + col0 + (tx << 2)) =
                make_float4(acc[r][0], acc[r][1], acc[r][2], acc[r][3]);
        }
    } else {
#pragma unroll
        for (int r = 0; r < 4; r++) {
            int rr = row0 + (ty << 2) + r;
            if (rr < M) {
                int tok   = g_list[e * TT + rr];
                float wgt = g_wt[e * TT + rr];
                float* op = out + (size_t)tok * HH + col0 + (tx << 2);
                atomicAdd(op + 0, wgt * acc[r][0]);
                atomicAdd(op + 1, wgt * acc[r][1]);
                atomicAdd(op + 2, wgt * acc[r][2]);
                atomicAdd(op + 3, wgt * acc[r][3]);
            }
        }
    }
}

/* persistent GRU scan: 128 blocks, W_hh slice resident in SMEM, grid barrier */
__global__ __launch_bounds__(256) void gru_kernel(const float* __restrict__ whh) {
    extern __shared__ float sW[];     /* 24 x 1024 floats */
    int tid = threadIdx.x;
    int c0  = blockIdx.x * 8;
#pragma unroll
    for (int r = 0; r < 24; r++) {
        int gate = r >> 3, j = r & 7;
        const float4* src = (const float4*)(whh + (size_t)(gate * GG + c0 + j) * GG);
        ((float4*)(sW + r * 1024))[tid] = src[tid];
    }
    __syncthreads();

    int w = tid >> 5, lane = tid & 31;
    int c = c0 + w;
    float pxr0 = 0.f, pxz0 = 0.f, pxn0 = 0.f, pxr1 = 0.f, pxz1 = 0.f, pxn1 = 0.f;
    float hold0 = 0.f, hold1 = 0.f;
    if (lane == 0) {
        pxr0 = g_xw[c]; pxz0 = g_xw[1024 + c]; pxn0 = g_xw[2048 + c];
        size_t o1 = (size_t)SS * G3;
        pxr1 = g_xw[o1 + c]; pxz1 = g_xw[o1 + 1024 + c]; pxn1 = g_xw[o1 + 2048 + c];
        hold0 = g_h[0][c]; hold1 = g_h[0][GG + c];
    }

    for (int t = 0; t < SS; t++) {
        int cur = t & 1, nxt = cur ^ 1;
        const float4* hg = (const float4*)(&g_h[cur][0]);
        float4 h0v[8], h1v[8];
#pragma unroll
        for (int i = 0; i < 8; i++) {
            h0v[i] = __ldcg(&hg[lane + 32 * i]);
            h1v[i] = __ldcg(&hg[256 + lane + 32 * i]);
        }
        float d0[3], d1[3];
#pragma unroll
        for (int g = 0; g < 3; g++) {
            const float4* wr = (const float4*)(sW + (g * 8 + w) * 1024);
            float a0 = 0.f, a1 = 0.f;
#pragma unroll
            for (int i = 0; i < 8; i++) {
                float4 wv = wr[lane + 32 * i];
                a0 = fmaf(wv.x, h0v[i].x, a0); a0 = fmaf(wv.y, h0v[i].y, a0);
                a0 = fmaf(wv.z, h0v[i].z, a0); a0 = fmaf(wv.w, h0v[i].w, a0);
                a1 = fmaf(wv.x, h1v[i].x, a1); a1 = fmaf(wv.y, h1v[i].y, a1);
                a1 = fmaf(wv.z, h1v[i].z, a1); a1 = fmaf(wv.w, h1v[i].w, a1);
            }
#pragma unroll
            for (int o = 16; o > 0; o >>= 1) {
                a0 += __shfl_xor_sync(0xffffffffu, a0, o);
                a1 += __shfl_xor_sync(0xffffffffu, a1, o);
            }
            d0[g] = a0; d1[g] = a1;
        }
        if (lane == 0) {
            float r0 = sigf(pxr0 + d0[0]);
            float z0 = sigf(pxz0 + d0[1]);
            float n0 = tanhf(pxn0 + r0 * d0[2]);
            float hn0 = (1.0f - z0) * n0 + z0 * hold0;
            float r1 = sigf(pxr1 + d1[0]);
            float z1 = sigf(pxz1 + d1[1]);
            float n1 = tanhf(pxn1 + r1 * d1[2]);
            float hn1 = (1.0f - z1) * n1 + z1 * hold1;
            g_h[nxt][c] = hn0; g_h[nxt][GG + c] = hn1;
            g_hs[(size_t)t * GG + c] = hn0;
            g_hs[(size_t)(SS + t) * GG + c] = hn1;
            hold0 = hn0; hold1 = hn1;
            if (t + 1 < SS) {
                size_t o0 = (size_t)(t + 1) * G3;
                size_t o1 = (size_t)(SS + t + 1) * G3;
                pxr0 = g_xw[o0 + c]; pxz0 = g_xw[o0 + 1024 + c]; pxn0 = g_xw[o0 + 2048 + c];
                pxr1 = g_xw[o1 + c]; pxz1 = g_xw[o1 + 1024 + c]; pxn1 = g_xw[o1 + 2048 + c];
            }
        }
        __syncthreads();
        if (tid == 0) {
            __threadfence();
            atomicAdd(&g_bar, 1u);
            unsigned int target = (unsigned int)GRU_BLOCKS * (unsigned int)(t + 1);
            while (ld_vol(&g_bar) < target) { __nanosleep(64); }
            __threadfence();
        }
        __syncthreads();
    }
}

/* scores = 9*(1-cos); top-2 -> softmax -> per-expert dispatch lists */
__global__ void score_kernel() {
    int wid  = (blockIdx.x * blockDim.x + threadIdx.x) >> 5;
    int lane = threadIdx.x & 31;
    if (wid >= TT) return;
    const float4* r4 = (const float4*)(g_hs   + (size_t)wid * GG);
    const float4* x4 = (const float4*)(g_expr + (size_t)wid * GG);
    float sc[EE];
#pragma unroll
    for (int e = 0; e < EE; e++) {
        float4 rv = r4[e * 32 + lane];
        float4 xv = x4[e * 32 + lane];
        float rr = rv.x * rv.x + rv.y * rv.y + rv.z * rv.z + rv.w * rv.w;
        float xx = xv.x * xv.x + xv.y * xv.y + xv.z * xv.z + xv.w * xv.w;
        float rx = rv.x * xv.x + rv.y * xv.y + rv.z * xv.z + rv.w * xv.w;
#pragma unroll
        for (int o = 16; o > 0; o >>= 1) {
            rr += __shfl_xor_sync(0xffffffffu, rr, o);
            xx += __shfl_xor_sync(0xffffffffu, xx, o);
            rx += __shfl_xor_sync(0xffffffffu, rx, o);
        }
        float nr  = sqrtf(rr);
        float nrc = fmaxf(nr, 1e-12f);
        float num = rx / nrc;
        float rn  = nr / nrc;
        float den = fmaxf(sqrtf(xx), 1e-8f) * fmaxf(rn, 1e-8f);
        sc[e] = (1.0f - num / den) * 9.0f;
    }
    if (lane == 0) {
        float v1 = -1e30f, v2 = -1e30f; int i1 = 0, i2 = 0;
#pragma unroll
        for (int e = 0; e < EE; e++) {
            float s = sc[e];
            if (s > v1) { v2 = v1; i2 = i1; v1 = s; i1 = e; }
            else if (s > v2) { v2 = s; i2 = e; }
        }
        float e2 = expf(v2 - v1);
        float w1 = 1.0f / (1.0f + e2);
        float w2 = e2 * w1;
        int p1 = atomicAdd(&g_cnt[i1], 1);
        g_list[i1 * TT + p1] = wid;  g_wt[i1 * TT + p1] = w1;
        int p2 = atomicAdd(&g_cnt[i2], 1);
        g_list[i2 * TT + p2] = wid;  g_wt[i2 * TT + p2] = w2;
    }
}

extern "C" void kernel_launch(void* const* d_in, const int* in_sizes, int n_in,
                              void* d_out, int out_size) {
    const float* hid  = (const float*)d_in[0];
    const float* wih  = (const float*)d_in[1];
    const float* whh  = (const float*)d_in[2];
    const float* expw = (const float*)d_in[3];
    const float* ctxw = (const float*)d_in[4];
    const float* ctxb = (const float*)d_in[5];
    const float* gw   = (const float*)d_in[6];
    const float* uw   = (const float*)d_in[7];
    const float* dw   = (const float*)d_in[8];
    const float* sgw  = (const float*)d_in[9];
    const float* suw  = (const float*)d_in[10];
    const float* sdw  = (const float*)d_in[11];
    float* out = (float*)d_out;
    (void)in_sizes; (void)n_in; (void)out_size;

    cudaFuncSetAttribute(gru_kernel, cudaFuncAttributeMaxDynamicSharedMemorySize,
                         24 * 1024 * (int)sizeof(float));
    void *xwp = 0, *exprp = 0;
    cudaGetSymbolAddress(&xwp, g_xw);
    cudaGetSymbolAddress(&exprp, g_expr);

    init_kernel<<<1, 32>>>();
    mean_kernel<<<(BB * HH + 255) / 256, 256>>>(hid);
    h0_kernel<<<256, 256>>>(ctxw, ctxb);

    sgemm_nt<<<dim3(G3 / 64, TT / 64), 256>>>(hid, wih, (float*)xwp, TT, G3, HH);
    sgemm_nt<<<dim3(GG / 64, TT / 64), 256>>>(hid, expw, (float*)exprp, TT, GG, HH);

    gru_kernel<<<GRU_BLOCKS, 256, 24 * 1024 * sizeof(float)>>>(whh);

    score_kernel<<<TT / 8, 256>>>();

    /* shared expert: dense, slot EE, writes base of out */
    gateup_kernel<<<dim3(FF / 64, TT / 64, 1), 256>>>(hid, sgw, suw, 0);
    down_kernel<<<dim3(HH / 64, TT / 64, 1), 256>>>(sdw, out, 0);

    /* sparse experts: gathered rows, weighted atomicAdd into out */
    gateup_kernel<<<dim3(FF / 64, TT / 64, EE), 256>>>(hid, gw, uw, 1);
    down_kernel<<<dim3(HH / 64, TT / 64, EE), 256>>>(dw, out, 1);
}

// round 6
// speedup vs baseline: 1.2930x; 1.2930x over previous
#include <cuda_runtime.h>

#define BB    2
#define SS    2048
#define TT    4096
#define HH    1024
#define GG    1024
#define G3    3072
#define FF    2048
#define EE    8
#define GRU_BLOCKS 128

__device__ float g_xw[(size_t)TT * G3];
__device__ float g_hs[(size_t)TT * GG];
__device__ float g_expr[(size_t)TT * GG];
__device__ float g_act[(size_t)(EE + 1) * TT * FF];
__device__ float g_mean[BB * HH];
__device__ float g_h[2][BB * GG];
__device__ int   g_cnt[EE];
__device__ int   g_list[EE * TT];
__device__ float g_wt[EE * TT];
__device__ unsigned int g_bar;

__device__ __forceinline__ float sigf(float x) { return 1.0f / (1.0f + expf(-x)); }

__device__ __forceinline__ unsigned int f2tf(float x) {
    unsigned int r;
    asm("cvt.rna.tf32.f32 %0, %1;" : "=r"(r) : "f"(x));
    return r;
}

__device__ __forceinline__ void mma8(float* c, const unsigned int* a, const unsigned int* b) {
    asm volatile(
        "mma.sync.aligned.m16n8k8.row.col.f32.tf32.tf32.f32 "
        "{%0,%1,%2,%3},{%4,%5,%6,%7},{%8,%9},{%0,%1,%2,%3};"
        : "+f"(c[0]), "+f"(c[1]), "+f"(c[2]), "+f"(c[3])
        : "r"(a[0]), "r"(a[1]), "r"(a[2]), "r"(a[3]), "r"(b[0]), "r"(b[1]));
}

__global__ void init_kernel() {
    int i = threadIdx.x;
    if (i < EE) g_cnt[i] = 0;
    if (i == 0) g_bar = 0u;
}

__global__ void mean_kernel(const float* __restrict__ hid) {
    int idx = blockIdx.x * blockDim.x + threadIdx.x;
    if (idx >= BB * HH) return;
    int b = idx / HH, h = idx % HH;
    const float* p = hid + (size_t)b * SS * HH + h;
    float s0 = 0.f, s1 = 0.f, s2 = 0.f, s3 = 0.f;
    for (int s = 0; s < SS; s += 4) {
        s0 += p[(size_t)(s + 0) * HH];
        s1 += p[(size_t)(s + 1) * HH];
        s2 += p[(size_t)(s + 2) * HH];
        s3 += p[(size_t)(s + 3) * HH];
    }
    g_mean[idx] = (s0 + s1 + s2 + s3) * (1.0f / (float)SS);
}

__global__ void h0_kernel(const float* __restrict__ ctxw, const float* __restrict__ ctxb) {
    int wid  = (blockIdx.x * blockDim.x + threadIdx.x) >> 5;
    int lane = threadIdx.x & 31;
    if (wid >= BB * GG) return;
    int b = wid >> 10, g = wid & 1023;
    const float4* wv = (const float4*)(ctxw + (size_t)g * HH);
    const float4* mv = (const float4*)(g_mean + b * HH);
    float acc = 0.f;
#pragma unroll
    for (int i = 0; i < 8; i++) {
        float4 a = wv[lane + 32 * i];
        float4 m = mv[lane + 32 * i];
        acc += a.x * m.x + a.y * m.y + a.z * m.z + a.w * m.w;
    }
#pragma unroll
    for (int o = 16; o > 0; o >>= 1) acc += __shfl_xor_sync(0xffffffffu, acc, o);
    if (lane == 0) g_h[0][b * GG + g] = acc + ctxb[g];
}

/* fp32 SIMT GEMM for the router path (precision-critical). C=A@B^T */
__global__ __launch_bounds__(256) void sgemm_nt(
    const float* __restrict__ A, const float* __restrict__ B, float* __restrict__ C,
    int M, int N, int K)
{
    __shared__ float As[16][68];
    __shared__ float Bs[16][68];
    int tid  = threadIdx.x;
    int row0 = blockIdx.y * 64, col0 = blockIdx.x * 64;
    int lm = tid >> 2, lk = (tid & 3) << 2;
    const float* Ap = A + (size_t)(row0 + lm) * K + lk;
    const float* Bp = B + (size_t)(col0 + lm) * K + lk;
    int ty = tid >> 4, tx = tid & 15;
    float acc[4][4] = {};
    for (int k0 = 0; k0 < K; k0 += 16) {
        float4 av = *(const float4*)(Ap + k0);
        float4 bv = *(const float4*)(Bp + k0);
        As[lk + 0][lm] = av.x; As[lk + 1][lm] = av.y; As[lk + 2][lm] = av.z; As[lk + 3][lm] = av.w;
        Bs[lk + 0][lm] = bv.x; Bs[lk + 1][lm] = bv.y; Bs[lk + 2][lm] = bv.z; Bs[lk + 3][lm] = bv.w;
        __syncthreads();
#pragma unroll
        for (int kk = 0; kk < 16; kk++) {
            float4 a = *(const float4*)(&As[kk][ty << 2]);
            float4 b = *(const float4*)(&Bs[kk][tx << 2]);
            float aa[4] = {a.x, a.y, a.z, a.w};
            float bb[4] = {b.x, b.y, b.z, b.w};
#pragma unroll
            for (int i = 0; i < 4; i++)
#pragma unroll
                for (int j = 0; j < 4; j++)
                    acc[i][j] = fmaf(aa[i], bb[j], acc[i][j]);
        }
        __syncthreads();
    }
#pragma unroll
    for (int i = 0; i < 4; i++)
        *(float4*)(C + (size_t)(row0 + (ty << 2) + i) * N + col0 + (tx << 2)) =
            make_float4(acc[i][0], acc[i][1], acc[i][2], acc[i][3]);
}

/* ===== TF32 tensor-core MLP GEMMs ===== */
/* CTA tile 128(M) x 64(N), 8 warps (2M x 4N), warp tile 64x16, mma m16n8k8. */
#define ASTR 36

/* act = silu(X Gw^T) * (X Uw^T). gather=0: dense M=TT, slot EE. */
__global__ __launch_bounds__(256, 1) void gateup_mma(
    const float* __restrict__ X,
    const float* __restrict__ gw_base, const float* __restrict__ uw_base, int gather)
{
    int e = blockIdx.z;
    int M = gather ? g_cnt[e] : TT;
    int row0 = blockIdx.y * 128;
    if (row0 >= M) return;
    int col0 = blockIdx.x * 64;
    const float* gwp = gw_base + (size_t)e * FF * HH;
    const float* uwp = uw_base + (size_t)e * FF * HH;
    float* actout = g_act + (size_t)(gather ? e : EE) * TT * FF;

    __shared__ float As[128 * ASTR];
    __shared__ float Gs[64 * ASTR];
    __shared__ float Us[64 * ASTR];
    __shared__ int rs[128];

    int tid = threadIdx.x;
    if (tid < 128) {
        int r = row0 + tid;
        rs[tid] = gather ? g_list[e * TT + min(r, M - 1)] : r;
    }
    __syncthreads();

    int w = tid >> 5, lane = tid & 31;
    int wm = w >> 2, wn = w & 3;
    int gid = lane >> 2, tig = lane & 3;

    float accg[4][2][4] = {};
    float accu[4][2][4] = {};

    float4 ra[4], rg[2], ru[2];
    /* prologue load: chunk k0=0 */
#pragma unroll
    for (int i = 0; i < 4; i++) {
        int j = tid + 256 * i, r = j >> 3, q = j & 7;
        ra[i] = *(const float4*)(X + (size_t)rs[r] * HH + q * 4);
    }
#pragma unroll
    for (int i = 0; i < 2; i++) {
        int j = tid + 256 * i, r = j >> 3, q = j & 7;
        rg[i] = *(const float4*)(gwp + (size_t)(col0 + r) * HH + q * 4);
        ru[i] = *(const float4*)(uwp + (size_t)(col0 + r) * HH + q * 4);
    }

    for (int k0 = 0; k0 < HH; k0 += 32) {
        /* store regs -> smem (converted to tf32) */
#pragma unroll
        for (int i = 0; i < 4; i++) {
            int j = tid + 256 * i, r = j >> 3, q = j & 7;
            float* d = &As[r * ASTR + q * 4];
            d[0] = __uint_as_float(f2tf(ra[i].x));
            d[1] = __uint_as_float(f2tf(ra[i].y));
            d[2] = __uint_as_float(f2tf(ra[i].z));
            d[3] = __uint_as_float(f2tf(ra[i].w));
        }
#pragma unroll
        for (int i = 0; i < 2; i++) {
            int j = tid + 256 * i, r = j >> 3, q = j & 7;
            float* dg = &Gs[r * ASTR + q * 4];
            float* du = &Us[r * ASTR + q * 4];
            dg[0] = __uint_as_float(f2tf(rg[i].x)); dg[1] = __uint_as_float(f2tf(rg[i].y));
            dg[2] = __uint_as_float(f2tf(rg[i].z)); dg[3] = __uint_as_float(f2tf(rg[i].w));
            du[0] = __uint_as_float(f2tf(ru[i].x)); du[1] = __uint_as_float(f2tf(ru[i].y));
            du[2] = __uint_as_float(f2tf(ru[i].z)); du[3] = __uint_as_float(f2tf(ru[i].w));
        }
        __syncthreads();
        /* prefetch next chunk */
        if (k0 + 32 < HH) {
            int kn = k0 + 32;
#pragma unroll
            for (int i = 0; i < 4; i++) {
                int j = tid + 256 * i, r = j >> 3, q = j & 7;
                ra[i] = *(const float4*)(X + (size_t)rs[r] * HH + kn + q * 4);
            }
#pragma unroll
            for (int i = 0; i < 2; i++) {
                int j = tid + 256 * i, r = j >> 3, q = j & 7;
                rg[i] = *(const float4*)(gwp + (size_t)(col0 + r) * HH + kn + q * 4);
                ru[i] = *(const float4*)(uwp + (size_t)(col0 + r) * HH + kn + q * 4);
            }
        }
        /* compute */
#pragma unroll
        for (int ks = 0; ks < 32; ks += 8) {
            unsigned int a[4][4], bg[2][2], bu[2][2];
#pragma unroll
            for (int mt = 0; mt < 4; mt++) {
                int r = wm * 64 + mt * 16 + gid;
                a[mt][0] = __float_as_uint(As[r * ASTR + ks + tig]);
                a[mt][1] = __float_as_uint(As[(r + 8) * ASTR + ks + tig]);
                a[mt][2] = __float_as_uint(As[r * ASTR + ks + tig + 4]);
                a[mt][3] = __float_as_uint(As[(r + 8) * ASTR + ks + tig + 4]);
            }
#pragma unroll
            for (int nt = 0; nt < 2; nt++) {
                int cc = wn * 16 + nt * 8 + gid;
                bg[nt][0] = __float_as_uint(Gs[cc * ASTR + ks + tig]);
                bg[nt][1] = __float_as_uint(Gs[cc * ASTR + ks + tig + 4]);
                bu[nt][0] = __float_as_uint(Us[cc * ASTR + ks + tig]);
                bu[nt][1] = __float_as_uint(Us[cc * ASTR + ks + tig + 4]);
            }
#pragma unroll
            for (int mt = 0; mt < 4; mt++)
#pragma unroll
                for (int nt = 0; nt < 2; nt++) {
                    mma8(accg[mt][nt], a[mt], bg[nt]);
                    mma8(accu[mt][nt], a[mt], bu[nt]);
                }
        }
        __syncthreads();
    }
    /* epilogue: silu(g)*u */
#pragma unroll
    for (int mt = 0; mt < 4; mt++)
#pragma unroll
        for (int nt = 0; nt < 2; nt++) {
            int rl0 = wm * 64 + mt * 16 + gid;
            int col = col0 + wn * 16 + nt * 8 + tig * 2;
            float g0 = accg[mt][nt][0], g1 = accg[mt][nt][1];
            float g2 = accg[mt][nt][2], g3 = accg[mt][nt][3];
            float2 lo, hi;
            lo.x = (g0 / (1.0f + expf(-g0))) * accu[mt][nt][0];
            lo.y = (g1 / (1.0f + expf(-g1))) * accu[mt][nt][1];
            hi.x = (g2 / (1.0f + expf(-g2))) * accu[mt][nt][2];
            hi.y = (g3 / (1.0f + expf(-g3))) * accu[mt][nt][3];
            int rr0 = row0 + rl0, rr1 = rr0 + 8;
            if (rr0 < M) *(float2*)(actout + (size_t)rr0 * FF + col) = lo;
            if (rr1 < M) *(float2*)(actout + (size_t)rr1 * FF + col) = hi;
        }
}

/* Y = act @ Dw^T. gather=0: plain store. gather=1: weighted atomicAdd. */
__global__ __launch_bounds__(256, 1) void down_mma(
    const float* __restrict__ dw_base, float* __restrict__ out, int gather)
{
    int e = blockIdx.z;
    int M = gather ? g_cnt[e] : TT;
    int row0 = blockIdx.y * 128;
    if (row0 >= M) return;
    int col0 = blockIdx.x * 64;
    const float* Aact = g_act + (size_t)(gather ? e : EE) * TT * FF;
    const float* dwp  = dw_base + (size_t)e * HH * FF;

    __shared__ float As[128 * ASTR];
    __shared__ float Bs[64 * ASTR];

    int tid = threadIdx.x;
    int w = tid >> 5, lane = tid & 31;
    int wm = w >> 2, wn = w & 3;
    int gid = lane >> 2, tig = lane & 3;

    float acc[4][2][4] = {};
    float4 ra[4], rb[2];
#pragma unroll
    for (int i = 0; i < 4; i++) {
        int j = tid + 256 * i, r = j >> 3, q = j & 7;
        int rsrc = min(row0 + r, M - 1);
        ra[i] = *(const float4*)(Aact + (size_t)rsrc * FF + q * 4);
    }
#pragma unroll
    for (int i = 0; i < 2; i++) {
        int j = tid + 256 * i, r = j >> 3, q = j & 7;
        rb[i] = *(const float4*)(dwp + (size_t)(col0 + r) * FF + q * 4);
    }

    for (int k0 = 0; k0 < FF; k0 += 32) {
#pragma unroll
        for (int i = 0; i < 4; i++) {
            int j = tid + 256 * i, r = j >> 3, q = j & 7;
            float* d = &As[r * ASTR + q * 4];
            d[0] = __uint_as_float(f2tf(ra[i].x));
            d[1] = __uint_as_float(f2tf(ra[i].y));
            d[2] = __uint_as_float(f2tf(ra[i].z));
            d[3] = __uint_as_float(f2tf(ra[i].w));
        }
#pragma unroll
        for (int i = 0; i < 2; i++) {
            int j = tid + 256 * i, r = j >> 3, q = j & 7;
            float* d = &Bs[r * ASTR + q * 4];
            d[0] = __uint_as_float(f2tf(rb[i].x));
            d[1] = __uint_as_float(f2tf(rb[i].y));
            d[2] = __uint_as_float(f2tf(rb[i].z));
            d[3] = __uint_as_float(f2tf(rb[i].w));
        }
        __syncthreads();
        if (k0 + 32 < FF) {
            int kn = k0 + 32;
#pragma unroll
            for (int i = 0; i < 4; i++) {
                int j = tid + 256 * i, r = j >> 3, q = j & 7;
                int rsrc = min(row0 + r, M - 1);
                ra[i] = *(const float4*)(Aact + (size_t)rsrc * FF + kn + q * 4);
            }
#pragma unroll
            for (int i = 0; i < 2; i++) {
                int j = tid + 256 * i, r = j >> 3, q = j & 7;
                rb[i] = *(const float4*)(dwp + (size_t)(col0 + r) * FF + kn + q * 4);
            }
        }
#pragma unroll
        for (int ks = 0; ks < 32; ks += 8) {
            unsigned int a[4][4], b[2][2];
#pragma unroll
            for (int mt = 0; mt < 4; mt++) {
                int r = wm * 64 + mt * 16 + gid;
                a[mt][0] = __float_as_uint(As[r * ASTR + ks + tig]);
                a[mt][1] = __float_as_uint(As[(r + 8) * ASTR + ks + tig]);
                a[mt][2] = __float_as_uint(As[r * ASTR + ks + tig + 4]);
                a[mt][3] = __float_as_uint(As[(r + 8) * ASTR + ks + tig + 4]);
            }
#pragma unroll
            for (int nt = 0; nt < 2; nt++) {
                int cc = wn * 16 + nt * 8 + gid;
                b[nt][0] = __float_as_uint(Bs[cc * ASTR + ks + tig]);
                b[nt][1] = __float_as_uint(Bs[cc * ASTR + ks + tig + 4]);
            }
#pragma unroll
            for (int mt = 0; mt < 4; mt++)
#pragma unroll
                for (int nt = 0; nt < 2; nt++)
                    mma8(acc[mt][nt], a[mt], b[nt]);
        }
        __syncthreads();
    }
#pragma unroll
    for (int mt = 0; mt < 4; mt++)
#pragma unroll
        for (int nt = 0; nt < 2; nt++) {
            int rl0 = wm * 64 + mt * 16 + gid;
            int col = col0 + wn * 16 + nt * 8 + tig * 2;
            int rr0 = row0 + rl0, rr1 = rr0 + 8;
            if (!gather) {
                *(float2*)(out + (size_t)rr0 * HH + col) =
                    make_float2(acc[mt][nt][0], acc[mt][nt][1]);
                *(float2*)(out + (size_t)rr1 * HH + col) =
                    make_float2(acc[mt][nt][2], acc[mt][nt][3]);
            } else {
                if (rr0 < M) {
                    int tok = g_list[e * TT + rr0]; float wgt = g_wt[e * TT + rr0];
                    float* op = out + (size_t)tok * HH + col;
                    atomicAdd(op + 0, wgt * acc[mt][nt][0]);
                    atomicAdd(op + 1, wgt * acc[mt][nt][1]);
                }
                if (rr1 < M) {
                    int tok = g_list[e * TT + rr1]; float wgt = g_wt[e * TT + rr1];
                    float* op = out + (size_t)tok * HH + col;
                    atomicAdd(op + 0, wgt * acc[mt][nt][2]);
                    atomicAdd(op + 1, wgt * acc[mt][nt][3]);
                }
            }
        }
}

/* persistent GRU scan: 128 blocks, W_hh slice in SMEM, release/acquire barrier */
__global__ __launch_bounds__(256) void gru_kernel(const float* __restrict__ whh) {
    extern __shared__ float sW[];
    int tid = threadIdx.x;
    int c0  = blockIdx.x * 8;
#pragma unroll
    for (int r = 0; r < 24; r++) {
        int gate = r >> 3, j = r & 7;
        const float4* src = (const float4*)(whh + (size_t)(gate * GG + c0 + j) * GG);
        ((float4*)(sW + r * 1024))[tid] = src[tid];
    }
    __syncthreads();

    int w = tid >> 5, lane = tid & 31;
    int c = c0 + w;
    float pxr0 = 0.f, pxz0 = 0.f, pxn0 = 0.f, pxr1 = 0.f, pxz1 = 0.f, pxn1 = 0.f;
    float hold0 = 0.f, hold1 = 0.f;
    if (lane == 0) {
        pxr0 = g_xw[c]; pxz0 = g_xw[1024 + c]; pxn0 = g_xw[2048 + c];
        size_t o1 = (size_t)SS * G3;
        pxr1 = g_xw[o1 + c]; pxz1 = g_xw[o1 + 1024 + c]; pxn1 = g_xw[o1 + 2048 + c];
        hold0 = g_h[0][c]; hold1 = g_h[0][GG + c];
    }

    for (int t = 0; t < SS; t++) {
        int cur = t & 1, nxt = cur ^ 1;
        const float4* hg = (const float4*)(&g_h[cur][0]);
        float4 h0v[8], h1v[8];
#pragma unroll
        for (int i = 0; i < 8; i++) {
            h0v[i] = __ldcg(&hg[lane + 32 * i]);
            h1v[i] = __ldcg(&hg[256 + lane + 32 * i]);
        }
        float d0[3], d1[3];
#pragma unroll
        for (int g = 0; g < 3; g++) {
            const float4* wr = (const float4*)(sW + (g * 8 + w) * 1024);
            float a0 = 0.f, a1 = 0.f;
#pragma unroll
            for (int i = 0; i < 8; i++) {
                float4 wv = wr[lane + 32 * i];
                a0 = fmaf(wv.x, h0v[i].x, a0); a0 = fmaf(wv.y, h0v[i].y, a0);
                a0 = fmaf(wv.z, h0v[i].z, a0); a0 = fmaf(wv.w, h0v[i].w, a0);
                a1 = fmaf(wv.x, h1v[i].x, a1); a1 = fmaf(wv.y, h1v[i].y, a1);
                a1 = fmaf(wv.z, h1v[i].z, a1); a1 = fmaf(wv.w, h1v[i].w, a1);
            }
#pragma unroll
            for (int o = 16; o > 0; o >>= 1) {
                a0 += __shfl_xor_sync(0xffffffffu, a0, o);
                a1 += __shfl_xor_sync(0xffffffffu, a1, o);
            }
            d0[g] = a0; d1[g] = a1;
        }
        if (lane == 0) {
            float r0 = sigf(pxr0 + d0[0]);
            float z0 = sigf(pxz0 + d0[1]);
            float n0 = tanhf(pxn0 + r0 * d0[2]);
            float hn0 = (1.0f - z0) * n0 + z0 * hold0;
            float r1 = sigf(pxr1 + d1[0]);
            float z1 = sigf(pxz1 + d1[1]);
            float n1 = tanhf(pxn1 + r1 * d1[2]);
            float hn1 = (1.0f - z1) * n1 + z1 * hold1;
            g_h[nxt][c] = hn0; g_h[nxt][GG + c] = hn1;
            g_hs[(size_t)t * GG + c] = hn0;
            g_hs[(size_t)(SS + t) * GG + c] = hn1;
            hold0 = hn0; hold1 = hn1;
            if (t + 1 < SS) {
                size_t o0 = (size_t)(t + 1) * G3;
                size_t o1 = (size_t)(SS + t + 1) * G3;
                pxr0 = g_xw[o0 + c]; pxz0 = g_xw[o0 + 1024 + c]; pxn0 = g_xw[o0 + 2048 + c];
                pxr1 = g_xw[o1 + c]; pxz1 = g_xw[o1 + 1024 + c]; pxn1 = g_xw[o1 + 2048 + c];
            }
        }
        __syncthreads();
        if (tid == 0) {
            asm volatile("red.release.gpu.global.add.u32 [%0], 1;"
                         :: "l"(&g_bar) : "memory");
            unsigned int target = (unsigned int)GRU_BLOCKS * (unsigned int)(t + 1);
            unsigned int v;
            do {
                asm volatile("ld.acquire.gpu.global.u32 %0, [%1];"
                             : "=r"(v) : "l"(&g_bar) : "memory");
            } while (v < target);
        }
        __syncthreads();
    }
}

/* scores = 9*(1-cos); top-2 softmax dispatch */
__global__ void score_kernel() {
    int wid  = (blockIdx.x * blockDim.x + threadIdx.x) >> 5;
    int lane = threadIdx.x & 31;
    if (wid >= TT) return;
    const float4* r4 = (const float4*)(g_hs   + (size_t)wid * GG);
    const float4* x4 = (const float4*)(g_expr + (size_t)wid * GG);
    float sc[EE];
#pragma unroll
    for (int e = 0; e < EE; e++) {
        float4 rv = r4[e * 32 + lane];
        float4 xv = x4[e * 32 + lane];
        float rr = rv.x * rv.x + rv.y * rv.y + rv.z * rv.z + rv.w * rv.w;
        float xx = xv.x * xv.x + xv.y * xv.y + xv.z * xv.z + xv.w * xv.w;
        float rx = rv.x * xv.x + rv.y * xv.y + rv.z * xv.z + rv.w * xv.w;
#pragma unroll
        for (int o = 16; o > 0; o >>= 1) {
            rr += __shfl_xor_sync(0xffffffffu, rr, o);
            xx += __shfl_xor_sync(0xffffffffu, xx, o);
            rx += __shfl_xor_sync(0xffffffffu, rx, o);
        }
        float nr  = sqrtf(rr);
        float nrc = fmaxf(nr, 1e-12f);
        float num = rx / nrc;
        float rn  = nr / nrc;
        float den = fmaxf(sqrtf(xx), 1e-8f) * fmaxf(rn, 1e-8f);
        sc[e] = (1.0f - num / den) * 9.0f;
    }
    if (lane == 0) {
        float v1 = -1e30f, v2 = -1e30f; int i1 = 0, i2 = 0;
#pragma unroll
        for (int e = 0; e < EE; e++) {
            float s = sc[e];
            if (s > v1) { v2 = v1; i2 = i1; v1 = s; i1 = e; }
            else if (s > v2) { v2 = s; i2 = e; }
        }
        float e2 = expf(v2 - v1);
        float w1 = 1.0f / (1.0f + e2);
        float w2 = e2 * w1;
        int p1 = atomicAdd(&g_cnt[i1], 1);
        g_list[i1 * TT + p1] = wid;  g_wt[i1 * TT + p1] = w1;
        int p2 = atomicAdd(&g_cnt[i2], 1);
        g_list[i2 * TT + p2] = wid;  g_wt[i2 * TT + p2] = w2;
    }
}

extern "C" void kernel_launch(void* const* d_in, const int* in_sizes, int n_in,
                              void* d_out, int out_size) {
    const float* hid  = (const float*)d_in[0];
    const float* wih  = (const float*)d_in[1];
    const float* whh  = (const float*)d_in[2];
    const float* expw = (const float*)d_in[3];
    const float* ctxw = (const float*)d_in[4];
    const float* ctxb = (const float*)d_in[5];
    const float* gw   = (const float*)d_in[6];
    const float* uw   = (const float*)d_in[7];
    const float* dw   = (const float*)d_in[8];
    const float* sgw  = (const float*)d_in[9];
    const float* suw  = (const float*)d_in[10];
    const float* sdw  = (const float*)d_in[11];
    float* out = (float*)d_out;
    (void)in_sizes; (void)n_in; (void)out_size;

    cudaFuncSetAttribute(gru_kernel, cudaFuncAttributeMaxDynamicSharedMemorySize,
                         24 * 1024 * (int)sizeof(float));
    void *xwp = 0, *exprp = 0;
    cudaGetSymbolAddress(&xwp, g_xw);
    cudaGetSymbolAddress(&exprp, g_expr);

    init_kernel<<<1, 32>>>();
    mean_kernel<<<(BB * HH + 255) / 256, 256>>>(hid);
    h0_kernel<<<256, 256>>>(ctxw, ctxb);

    sgemm_nt<<<dim3(G3 / 64, TT / 64), 256>>>(hid, wih, (float*)xwp, TT, G3, HH);
    sgemm_nt<<<dim3(GG / 64, TT / 64), 256>>>(hid, expw, (float*)exprp, TT, GG, HH);

    gru_kernel<<<GRU_BLOCKS, 256, 24 * 1024 * sizeof(float)>>>(whh);

    score_kernel<<<TT / 8, 256>>>();

    /* shared expert (dense, slot EE, writes base of out) */
    gateup_mma<<<dim3(FF / 64, TT / 128, 1), 256>>>(hid, sgw, suw, 0);
    down_mma<<<dim3(HH / 64, TT / 128, 1), 256>>>(sdw, out, 0);

    /* sparse experts (gathered rows, weighted atomicAdd) */
    gateup_mma<<<dim3(FF / 64, TT / 128, EE), 256>>>(hid, gw, uw, 1);
    down_mma<<<dim3(HH / 64, TT / 128, EE), 256>>>(dw, out, 1);
}